// round 2
// baseline (speedup 1.0000x reference)
#include <cuda_runtime.h>
#include <cstdint>

// Problem shape
#define NB 16
#define NQ 2048
#define NK 2048
#define ND 128
// Tiling
#define BQ 64
#define BK 64
#define NTHREADS 256
#define SD 132       // sQ/sK row stride in floats (bank-conflict padding)
#define SSTRIDE 68   // sS row stride in floats

typedef unsigned long long u64;

// 8 MB dropout bitmask scratch: bit idx = ((b*NQ+q)*NK + k), 1 = keep
__device__ unsigned int g_mask[(size_t)NB * NQ * NK / 32];

// ---------------------------------------------------------------------------
// f32x2 packed math (sm_100+; ptxas never auto-fuses, PTX only)
// ---------------------------------------------------------------------------
__device__ __forceinline__ u64 pk2(float lo, float hi) {
    u64 r; asm("mov.b64 %0, {%1, %2};" : "=l"(r) : "f"(lo), "f"(hi)); return r;
}
__device__ __forceinline__ void upk2(u64 v, float& lo, float& hi) {
    asm("mov.b64 {%0, %1}, %2;" : "=f"(lo), "=f"(hi) : "l"(v));
}
__device__ __forceinline__ u64 f2fma(u64 a, u64 b, u64 c) {
    u64 d; asm("fma.rn.f32x2 %0, %1, %2, %3;" : "=l"(d) : "l"(a), "l"(b), "l"(c)); return d;
}
__device__ __forceinline__ u64 f2mul(u64 a, u64 b) {
    u64 d; asm("mul.rn.f32x2 %0, %1, %2;" : "=l"(d) : "l"(a), "l"(b)); return d;
}

// ---------------------------------------------------------------------------
// JAX Threefry-2x32 (20 rounds), key = [0, 42] for jax.random.key(42)
// ---------------------------------------------------------------------------
__device__ __forceinline__ uint32_t rotl32(uint32_t x, uint32_t r) {
    return __funnelshift_l(x, x, r);
}

__device__ __forceinline__ void threefry2x32_0_42(uint32_t x0, uint32_t x1,
                                                  uint32_t& o0, uint32_t& o1) {
    const uint32_t ks0 = 0u, ks1 = 42u;
    const uint32_t ks2 = ks0 ^ ks1 ^ 0x1BD11BDAu;
    x0 += ks0; x1 += ks1;
#define TF_R(r) { x0 += x1; x1 = rotl32(x1, (r)); x1 ^= x0; }
    TF_R(13) TF_R(15) TF_R(26) TF_R(6)
    x0 += ks1; x1 += ks2 + 1u;
    TF_R(17) TF_R(29) TF_R(16) TF_R(24)
    x0 += ks2; x1 += ks0 + 2u;
    TF_R(13) TF_R(15) TF_R(26) TF_R(6)
    x0 += ks0; x1 += ks1 + 3u;
    TF_R(17) TF_R(29) TF_R(16) TF_R(24)
    x0 += ks1; x1 += ks2 + 4u;
    TF_R(13) TF_R(15) TF_R(26) TF_R(6)
    x0 += ks2; x1 += ks0 + 5u;
#undef TF_R
    o0 = x0; o1 = x1;
}

// JAX uniform-from-bits: u = bitcast((bits >> 9) | 0x3f800000) - 1.0 ; keep = u < 0.7f
__device__ __forceinline__ bool bern_keep(uint32_t bits) {
    float u = __uint_as_float((bits >> 9) | 0x3f800000u) - 1.0f;
    return u < 0.7f;
}

// PARTITIONABLE threefry (modern JAX default): per flat index i (uint64),
// counter = (hi32(i), lo32(i)) = (0, i) here since n = 2^26 < 2^32;
// 32-bit output = x0 ^ x1. One hash per output element, ballot-packed.
__global__ void mask_kernel() {
    uint32_t i = blockIdx.x * blockDim.x + threadIdx.x;   // [0, 2^26)
    uint32_t o0, o1;
    threefry2x32_0_42(0u, i, o0, o1);
    unsigned b = __ballot_sync(0xffffffffu, bern_keep(o0 ^ o1));
    if ((threadIdx.x & 31u) == 0u) g_mask[i >> 5] = b;
}

// ---------------------------------------------------------------------------
// Fused flash attention (fp32, online softmax, dropout from g_mask)
// ---------------------------------------------------------------------------
__global__ void __launch_bounds__(NTHREADS)
attn_kernel(const float* __restrict__ x1, const float* __restrict__ x2,
            float* __restrict__ out) {
    extern __shared__ float sm[];
    float* sQ  = sm;                    // [BQ][SD]
    float* sK  = sQ + BQ * SD;          // [BK][SD]
    float* sS  = sK + BQ * SD;          // [BQ][SSTRIDE]
    float* sM  = sS + BQ * SSTRIDE;     // [BQ]
    float* sL  = sM + BQ;               // [BQ]
    float* sAl = sL + BQ;               // [BQ]

    const int b  = blockIdx.y;
    const int q0 = blockIdx.x * BQ;
    const int tid = threadIdx.x;
    const int tx = tid & 15;            // 0..15
    const int ty = tid >> 4;            // 0..15  (rows ty*4 + i)

    // Load Q tile (64x128) coalesced float4
    const float* gq = x1 + (size_t)(b * NQ + q0) * ND;
    for (int t = tid; t < BQ * ND / 4; t += NTHREADS) {
        int row = t >> 5, c = (t & 31) << 2;
        *(float4*)(sQ + row * SD + c) = *(const float4*)(gq + row * ND + c);
    }
    if (tid < BQ) { sM[tid] = -1e30f; sL[tid] = 0.0f; }

    u64 oacc[4][4];                     // out cols = 2*tx + 32*j + {0,1}
#pragma unroll
    for (int i = 0; i < 4; i++)
#pragma unroll
        for (int j = 0; j < 4; j++) oacc[i][j] = 0ull;

    const int r = tid >> 2, part = tid & 3;   // softmax step: 4 lanes per row
    const unsigned mrow_base = (unsigned)(b * NQ + q0 + r) * (NK / 32);

    for (int kt = 0; kt < NK / BK; ++kt) {
        __syncthreads();                // prev GEMM2 done with sK/sS
        const int k0 = kt * BK;
        const float* gk = x2 + (size_t)(b * NK + k0) * ND;
        for (int t = tid; t < BK * ND / 4; t += NTHREADS) {
            int row = t >> 5, c = (t & 31) << 2;
            *(float4*)(sK + row * SD + c) = *(const float4*)(gk + row * ND + c);
        }
        __syncthreads();

        // ---- GEMM1: S[64x64] = Qtile @ Ktile^T, thread k-cols = tx + 16j
        u64 s2[4][4];
#pragma unroll
        for (int i = 0; i < 4; i++)
#pragma unroll
            for (int j = 0; j < 4; j++) s2[i][j] = 0ull;

        for (int d0 = 0; d0 < ND; d0 += 4) {
            float4 a4[4], b4[4];
#pragma unroll
            for (int i = 0; i < 4; i++)
                a4[i] = *(const float4*)(sQ + (ty * 4 + i) * SD + d0);
#pragma unroll
            for (int j = 0; j < 4; j++)
                b4[j] = *(const float4*)(sK + (tx + 16 * j) * SD + d0);
#pragma unroll
            for (int i = 0; i < 4; i++) {
                u64 alo = pk2(a4[i].x, a4[i].y);
                u64 ahi = pk2(a4[i].z, a4[i].w);
#pragma unroll
                for (int j = 0; j < 4; j++) {
                    s2[i][j] = f2fma(alo, pk2(b4[j].x, b4[j].y), s2[i][j]);
                    s2[i][j] = f2fma(ahi, pk2(b4[j].z, b4[j].w), s2[i][j]);
                }
            }
        }
#pragma unroll
        for (int i = 0; i < 4; i++)
#pragma unroll
            for (int j = 0; j < 4; j++) {
                float lo, hi; upk2(s2[i][j], lo, hi);
                sS[(ty * 4 + i) * SSTRIDE + tx + 16 * j] = (lo + hi) * 1.153f;
            }
        __syncthreads();

        // ---- Online softmax + dropout: 4 lanes x 16 cols per row
        {
            float mprev = sM[r], lprev = sL[r];
            float* srow = sS + r * SSTRIDE + part * 16;
            float v[16];
            float mx = -1e30f;
#pragma unroll
            for (int c = 0; c < 16; c++) { v[c] = srow[c]; mx = fmaxf(mx, v[c]); }
            mx = fmaxf(mx, __shfl_xor_sync(0xffffffffu, mx, 1));
            mx = fmaxf(mx, __shfl_xor_sync(0xffffffffu, mx, 2));
            float mnew = fmaxf(mprev, mx);
            unsigned mword = g_mask[mrow_base + ((unsigned)(k0 + part * 16) >> 5)];
            float sum = 0.0f;
#pragma unroll
            for (int c = 0; c < 16; c++) {
                float e = __expf(v[c] - mnew);
                sum += e;   // denominator uses UNmasked exp (softmax before dropout)
                srow[c] = ((mword >> ((part * 16 + c) & 31)) & 1u) ? e : 0.0f;
            }
            sum += __shfl_xor_sync(0xffffffffu, sum, 1);
            sum += __shfl_xor_sync(0xffffffffu, sum, 2);
            float alpha = __expf(mprev - mnew);
            if (part == 0) {
                sM[r] = mnew;
                sL[r] = lprev * alpha + sum;
                sAl[r] = alpha;
            }
        }
        __syncthreads();

        // ---- GEMM2: out += P[64x64] @ Vtile[64x128], cols 2tx+32j (f32x2)
#pragma unroll
        for (int i = 0; i < 4; i++) {
            float al = sAl[ty * 4 + i];
            u64 al2 = pk2(al, al);
#pragma unroll
            for (int j = 0; j < 4; j++) oacc[i][j] = f2mul(oacc[i][j], al2);
        }
#pragma unroll 2
        for (int kk0 = 0; kk0 < BK; kk0 += 4) {
            float4 p4[4];
#pragma unroll
            for (int i = 0; i < 4; i++)
                p4[i] = *(const float4*)(sS + (ty * 4 + i) * SSTRIDE + kk0);
#pragma unroll
            for (int dd = 0; dd < 4; dd++) {
                u64 v2[4];
#pragma unroll
                for (int j = 0; j < 4; j++)
                    v2[j] = *(const u64*)(sK + (kk0 + dd) * SD + 2 * tx + 32 * j);
#pragma unroll
                for (int i = 0; i < 4; i++) {
                    float pv = ((const float*)&p4[i])[dd];
                    u64 pb = pk2(pv, pv);
#pragma unroll
                    for (int j = 0; j < 4; j++)
                        oacc[i][j] = f2fma(pb, v2[j], oacc[i][j]);
                }
            }
        }
    }

    // ---- Epilogue: out = acc / (0.7f * l)
#pragma unroll
    for (int i = 0; i < 4; i++) {
        float inv = 1.0f / (0.7f * sL[ty * 4 + i]);
        u64 inv2 = pk2(inv, inv);
        float* grow = out + (size_t)(b * NQ + q0 + ty * 4 + i) * ND;
#pragma unroll
        for (int j = 0; j < 4; j++) {
            u64 o = f2mul(oacc[i][j], inv2);
            float lo, hi; upk2(o, lo, hi);
            float2 st; st.x = lo; st.y = hi;
            *(float2*)(grow + 2 * tx + 32 * j) = st;
        }
    }
}

// ---------------------------------------------------------------------------
extern "C" void kernel_launch(void* const* d_in, const int* in_sizes, int n_in,
                              void* d_out, int out_size) {
    const float* x1 = (const float*)d_in[0];
    const float* x2 = (const float*)d_in[1];
    float* out = (float*)d_out;

    // 1) dropout mask bits (partitionable threefry: one hash per element)
    mask_kernel<<<(1u << 26) / 256, 256>>>();

    // 2) fused attention
    size_t smem = (size_t)(2 * BQ * SD + BQ * SSTRIDE + 3 * BQ) * sizeof(float);
    cudaFuncSetAttribute(attn_kernel,
                         cudaFuncAttributeMaxDynamicSharedMemorySize, (int)smem);
    dim3 grid(NQ / BQ, NB);
    attn_kernel<<<grid, NTHREADS, smem>>>(x1, x2, out);
}

// round 3
// speedup vs baseline: 1.7908x; 1.7908x over previous
#include <cuda_runtime.h>
#include <cstdint>

// Problem shape
#define NB 16
#define NQ 2048
#define NK 2048
#define ND 128
// Tiling
#define BQ 64
#define BK 64
#define NTHREADS 256
#define SD 132       // sK row stride in floats (bank-conflict padding)
#define SQD 128      // sQ row stride (broadcast loads, no pad needed)
#define SSTRIDE 68   // sS (P tile) row stride in floats

typedef unsigned long long u64;

// ---------------------------------------------------------------------------
// f32x2 packed math (sm_100+; PTX only)
// ---------------------------------------------------------------------------
__device__ __forceinline__ u64 pk2(float lo, float hi) {
    u64 r; asm("mov.b64 %0, {%1, %2};" : "=l"(r) : "f"(lo), "f"(hi)); return r;
}
__device__ __forceinline__ void upk2(u64 v, float& lo, float& hi) {
    asm("mov.b64 {%0, %1}, %2;" : "=f"(lo), "=f"(hi) : "l"(v));
}
__device__ __forceinline__ u64 f2fma(u64 a, u64 b, u64 c) {
    u64 d; asm("fma.rn.f32x2 %0, %1, %2, %3;" : "=l"(d) : "l"(a), "l"(b), "l"(c)); return d;
}
__device__ __forceinline__ u64 f2mul(u64 a, u64 b) {
    u64 d; asm("mul.rn.f32x2 %0, %1, %2;" : "=l"(d) : "l"(a), "l"(b)); return d;
}

// ---------------------------------------------------------------------------
// JAX Threefry-2x32, key = [0, 42]; partitionable path: counter=(0, i),
// output bits = x0 ^ x1; keep <=> (bits>>9) < ceil(0.7f * 2^23)
// ---------------------------------------------------------------------------
__device__ __forceinline__ uint32_t rotl32(uint32_t x, uint32_t r) {
    return __funnelshift_l(x, x, r);
}

__device__ __forceinline__ bool keep_bit(uint32_t i) {
    const uint32_t ks1 = 42u;
    const uint32_t ks2 = 42u ^ 0x1BD11BDAu;
    uint32_t x0 = 0u, x1 = i + ks1;
#define TF_R(r) { x0 += x1; x1 = rotl32(x1, (r)); x1 ^= x0; }
    TF_R(13) TF_R(15) TF_R(26) TF_R(6)
    x0 += ks1; x1 += ks2 + 1u;
    TF_R(17) TF_R(29) TF_R(16) TF_R(24)
    x0 += ks2; x1 += 2u;
    TF_R(13) TF_R(15) TF_R(26) TF_R(6)
    x1 += ks1 + 3u;                 // x0 += ks0 (=0)
    TF_R(17) TF_R(29) TF_R(16) TF_R(24)
    x0 += ks1; x1 += ks2 + 4u;
    TF_R(13) TF_R(15) TF_R(26) TF_R(6)
    x0 += ks2; x1 += 5u;
#undef TF_R
    uint32_t bits = x0 ^ x1;
    return (bits >> 9) < 5872026u;  // u = (bits>>9)*2^-23 < 0.7f, exact
}

// ---------------------------------------------------------------------------
// Fused flash attention (fp32, register online softmax, inline threefry dropout)
// ---------------------------------------------------------------------------
__global__ void __launch_bounds__(NTHREADS, 2)
attn_kernel(const float* __restrict__ x1, const float* __restrict__ x2,
            float* __restrict__ out) {
    extern __shared__ float sm[];
    float* sQ = sm;                 // [BQ][SQD]
    float* sK = sQ + BQ * SQD;      // [BK][SD]
    float* sS = sK + BK * SD;       // [BQ][SSTRIDE]  (holds P, post-dropout exp)

    const int b  = blockIdx.y;
    const int q0 = blockIdx.x * BQ;
    const int tid = threadIdx.x;
    const int tx = tid & 15;        // 0..15
    const int ty = tid >> 4;        // 0..15  (rows ty*4 + i, all within one half-warp)

    // Load Q tile (64x128) coalesced float4
    const float* gq = x1 + (size_t)(b * NQ + q0) * ND;
    for (int t = tid; t < BQ * ND / 4; t += NTHREADS) {
        int row = t >> 5, c = (t & 31) << 2;
        *(float4*)(sQ + row * SQD + c) = *(const float4*)(gq + row * ND + c);
    }

    // Per-row online softmax state (uniform across each half-warp)
    float m_i[4], l_i[4];
    uint32_t rb[4];                 // threefry flat-index row bases
#pragma unroll
    for (int i = 0; i < 4; i++) {
        m_i[4 - 4 + i] = -1e30f;    // (plain init, kept explicit)
        l_i[i] = 0.0f;
        rb[i] = (uint32_t)(b * NQ + q0 + ty * 4 + i) * (uint32_t)NK;
    }
#pragma unroll
    for (int i = 0; i < 4; i++) m_i[i] = -1e30f;

    u64 oacc[4][4];                 // out cols = 2*tx + 32*j + {0,1}
#pragma unroll
    for (int i = 0; i < 4; i++)
#pragma unroll
        for (int j = 0; j < 4; j++) oacc[i][j] = 0ull;

    for (int kt = 0; kt < NK / BK; ++kt) {
        __syncthreads();            // prev GEMM2 done reading sK/sS
        const int k0 = kt * BK;
        const float* gk = x2 + (size_t)(b * NK + k0) * ND;
        for (int t = tid; t < BK * ND / 4; t += NTHREADS) {
            int row = t >> 5, c = (t & 31) << 2;
            *(float4*)(sK + row * SD + c) = *(const float4*)(gk + row * ND + c);
        }
        __syncthreads();            // K tile (and, on kt=0, Q tile) ready

        // ---- GEMM1: S[64x64] = Qtile @ Ktile^T; thread cols = tx + 16j
        u64 s2[4][4];
#pragma unroll
        for (int i = 0; i < 4; i++)
#pragma unroll
            for (int j = 0; j < 4; j++) s2[i][j] = 0ull;

        for (int d0 = 0; d0 < ND; d0 += 4) {
            float4 a4[4], b4[4];
#pragma unroll
            for (int i = 0; i < 4; i++)
                a4[i] = *(const float4*)(sQ + (ty * 4 + i) * SQD + d0);
#pragma unroll
            for (int j = 0; j < 4; j++)
                b4[j] = *(const float4*)(sK + (tx + 16 * j) * SD + d0);
            u64 blo[4], bhi[4];
#pragma unroll
            for (int j = 0; j < 4; j++) {
                blo[j] = pk2(b4[j].x, b4[j].y);
                bhi[j] = pk2(b4[j].z, b4[j].w);
            }
#pragma unroll
            for (int i = 0; i < 4; i++) {
                u64 alo = pk2(a4[i].x, a4[i].y);
                u64 ahi = pk2(a4[i].z, a4[i].w);
#pragma unroll
                for (int j = 0; j < 4; j++) {
                    s2[i][j] = f2fma(alo, blo[j], s2[i][j]);
                    s2[i][j] = f2fma(ahi, bhi[j], s2[i][j]);
                }
            }
        }

        // ---- Register online softmax + inline threefry dropout
        // Row ty*4+i lives entirely in this half-warp (cols tx+16j).
#pragma unroll
        for (int i = 0; i < 4; i++) {
            float s[4];
            float mx = -1e30f;
#pragma unroll
            for (int j = 0; j < 4; j++) {
                float lo, hi; upk2(s2[i][j], lo, hi);
                s[j] = (lo + hi) * 1.153f;
                mx = fmaxf(mx, s[j]);
            }
#pragma unroll
            for (int off = 1; off < 16; off <<= 1)
                mx = fmaxf(mx, __shfl_xor_sync(0xffffffffu, mx, off));
            float mnew  = fmaxf(m_i[i], mx);
            float alpha = __expf(m_i[i] - mnew);
            m_i[i] = mnew;

            float sum = 0.0f;
            float p[4];
            uint32_t base = rb[i] + (uint32_t)(k0 + tx);
#pragma unroll
            for (int j = 0; j < 4; j++) {
                float e = __expf(s[j] - mnew);
                sum += e;                       // denominator uses UNmasked exp
                p[j] = keep_bit(base + 16u * j) ? e : 0.0f;
            }
#pragma unroll
            for (int off = 1; off < 16; off <<= 1)
                sum += __shfl_xor_sync(0xffffffffu, sum, off);
            l_i[i] = l_i[i] * alpha + sum;

            float* srow = sS + (ty * 4 + i) * SSTRIDE;
#pragma unroll
            for (int j = 0; j < 4; j++) srow[tx + 16 * j] = p[j];

            u64 al2 = pk2(alpha, alpha);
#pragma unroll
            for (int j = 0; j < 4; j++) oacc[i][j] = f2mul(oacc[i][j], al2);
        }
        __syncthreads();            // P tile ready for all warps

        // ---- GEMM2: out += P[64x64] @ Vtile[64x128]; cols 2tx+32j (f32x2)
#pragma unroll 2
        for (int kk0 = 0; kk0 < BK; kk0 += 4) {
            float4 p4[4];
#pragma unroll
            for (int i = 0; i < 4; i++)
                p4[i] = *(const float4*)(sS + (ty * 4 + i) * SSTRIDE + kk0);
#pragma unroll
            for (int dd = 0; dd < 4; dd++) {
                u64 v2[4];
#pragma unroll
                for (int j = 0; j < 4; j++)
                    v2[j] = *(const u64*)(sK + (kk0 + dd) * SD + 2 * tx + 32 * j);
#pragma unroll
                for (int i = 0; i < 4; i++) {
                    float pv = ((const float*)&p4[i])[dd];
                    u64 pb = pk2(pv, pv);
#pragma unroll
                    for (int j = 0; j < 4; j++)
                        oacc[i][j] = f2fma(pb, v2[j], oacc[i][j]);
                }
            }
        }
    }

    // ---- Epilogue: out = acc / (0.7f * l)
#pragma unroll
    for (int i = 0; i < 4; i++) {
        float inv = 1.0f / (0.7f * l_i[i]);
        u64 inv2 = pk2(inv, inv);
        float* grow = out + (size_t)(b * NQ + q0 + ty * 4 + i) * ND;
#pragma unroll
        for (int j = 0; j < 4; j++) {
            u64 o = f2mul(oacc[i][j], inv2);
            float lo, hi; upk2(o, lo, hi);
            float2 st; st.x = lo; st.y = hi;
            *(float2*)(grow + 2 * tx + 32 * j) = st;
        }
    }
}

// ---------------------------------------------------------------------------
extern "C" void kernel_launch(void* const* d_in, const int* in_sizes, int n_in,
                              void* d_out, int out_size) {
    const float* x1 = (const float*)d_in[0];
    const float* x2 = (const float*)d_in[1];
    float* out = (float*)d_out;

    size_t smem = (size_t)(BQ * SQD + BK * SD + BQ * SSTRIDE) * sizeof(float); // 83.2 KB
    cudaFuncSetAttribute(attn_kernel,
                         cudaFuncAttributeMaxDynamicSharedMemorySize, (int)smem);
    dim3 grid(NQ / BQ, NB);
    attn_kernel<<<grid, NTHREADS, smem>>>(x1, x2, out);
}